// round 5
// baseline (speedup 1.0000x reference)
#include <cuda_runtime.h>
#include <cuda_bf16.h>
#include <cstdint>

// Problem shape (fixed by the reference): E edges, per edge:
//   out[o][t] = sum_n W[o][n] * x[n][t] + b[o],  O=N=64, T=256
#define N_DIM 64
#define O_DIM 64
#define T_DIM 256

__device__ __forceinline__ unsigned long long pack2(float a, float b) {
    unsigned long long r;
    asm("mov.b64 %0, {%1, %2};" : "=l"(r) : "f"(a), "f"(b));
    return r;
}

// packed dual-fp32 FMA (Blackwell f32x2 pipe; PTX-only, ptxas never auto-fuses)
__device__ __forceinline__ void ffma2(unsigned long long& d,
                                      unsigned long long a,
                                      unsigned long long b) {
    asm("fma.rn.f32x2 %0, %1, %2, %3;" : "=l"(d) : "l"(a), "l"(b), "l"(d));
}

// One CTA per edge. Stage x[e] (64x256 f32 = 64KB) and W[e] (64x64 f32 = 16KB)
// in dynamic smem, register-tile 8(o) x 8(t) per thread, accumulate in f32x2.
__global__ void __launch_bounds__(256, 2)
parallel_linear_kernel(const float* __restrict__ x,
                       const float* __restrict__ W,
                       const float* __restrict__ b,
                       float* __restrict__ out) {
    extern __shared__ float smem[];
    float* xs = smem;                      // [64][256]
    float* ws = smem + N_DIM * T_DIM;      // [64][64]

    const int e   = blockIdx.x;
    const int tid = threadIdx.x;

    const float* xg = x + (size_t)e * (N_DIM * T_DIM);
    const float* wg = W + (size_t)e * (O_DIM * N_DIM);
    const float* bg = b + (size_t)e * O_DIM;
    float*       og = out + (size_t)e * (O_DIM * T_DIM);

    // ---- Stage x[e] and W[e] into smem (coalesced float4) ----
    {
        const float4* xg4 = (const float4*)xg;
        float4*       xs4 = (float4*)xs;
        #pragma unroll
        for (int i = 0; i < (N_DIM * T_DIM / 4) / 256; ++i)   // 16 iters
            xs4[tid + i * 256] = xg4[tid + i * 256];

        const float4* wg4 = (const float4*)wg;
        float4*       ws4 = (float4*)ws;
        #pragma unroll
        for (int i = 0; i < (O_DIM * N_DIM / 4) / 256; ++i)   // 4 iters
            ws4[tid + i * 256] = wg4[tid + i * 256];
    }
    __syncthreads();

    // ---- Register tile: thread (tx, oy) computes o in [oy*8, oy*8+8),
    //      t in {tx*4..tx*4+3} U {128+tx*4..128+tx*4+3} ----
    const int tx = tid & 31;   // 0..31
    const int oy = tid >> 5;   // 0..7 (warp id -> W smem reads are warp-uniform => broadcast)
    const int t0 = tx * 4;
    const int ob = oy * 8;

    unsigned long long acc[8][4];
    #pragma unroll
    for (int i = 0; i < 8; ++i) {
        const float bv = bg[ob + i];
        const unsigned long long bp = pack2(bv, bv);
        acc[i][0] = bp; acc[i][1] = bp; acc[i][2] = bp; acc[i][3] = bp;
    }

    #pragma unroll 4
    for (int k = 0; k < N_DIM; ++k) {
        // x row k: two 16B loads, stride-16B contiguous across the warp => conflict-free
        const ulonglong2 xa = *(const ulonglong2*)(xs + k * T_DIM + t0);
        const ulonglong2 xb = *(const ulonglong2*)(xs + k * T_DIM + 128 + t0);

        #pragma unroll
        for (int i = 0; i < 8; ++i) {
            const float w = ws[(ob + i) * N_DIM + k];      // warp-uniform broadcast
            const unsigned long long wp = pack2(w, w);
            ffma2(acc[i][0], wp, xa.x);
            ffma2(acc[i][1], wp, xa.y);
            ffma2(acc[i][2], wp, xb.x);
            ffma2(acc[i][3], wp, xb.y);
        }
    }

    // ---- Store: two STG.128 per o-row, warp-contiguous 512B ----
    #pragma unroll
    for (int i = 0; i < 8; ++i) {
        const int o = ob + i;
        ulonglong2 v0; v0.x = acc[i][0]; v0.y = acc[i][1];
        ulonglong2 v1; v1.x = acc[i][2]; v1.y = acc[i][3];
        *(ulonglong2*)(og + o * T_DIM + t0)       = v0;
        *(ulonglong2*)(og + o * T_DIM + 128 + t0) = v1;
    }
}

extern "C" void kernel_launch(void* const* d_in, const int* in_sizes, int n_in,
                              void* d_out, int out_size) {
    const float* x = (const float*)d_in[0];   // [E, 64, 256]
    const float* W = (const float*)d_in[1];   // [E, 64, 64]
    const float* b = (const float*)d_in[2];   // [E, 64]
    float*       o = (float*)d_out;           // [E, 64, 256]

    const int E = in_sizes[0] / (N_DIM * T_DIM);

    const int smem_bytes = (N_DIM * T_DIM + O_DIM * N_DIM) * (int)sizeof(float); // 80KB
    cudaFuncSetAttribute(parallel_linear_kernel,
                         cudaFuncAttributeMaxDynamicSharedMemorySize, smem_bytes);

    parallel_linear_kernel<<<E, 256, smem_bytes>>>(x, W, b, o);
}

// round 9
// speedup vs baseline: 1.0498x; 1.0498x over previous
#include <cuda_runtime.h>
#include <cuda_bf16.h>
#include <cstdint>

// Per edge: out[o][t] = sum_k W[o][k] * x[k][t] + b[o],  O=K=64, T=256, E=10000
// mma.sync m16n8k16 bf16 (compiles under compute_103; tcgen05 does NOT):
//   D[t][o] = A[t][k] * B[k][o],  A = x^T (ldmatrix.trans on native x[k][t]),
//   B = W[o][k] row-major == B col-major (ldmatrix non-trans).
// 3-term bf16 split: D = xh*wh + xl*wh + xh*wl  (rel err ~2^-18)

#define T_DIM 256
#define K_DIM 64
#define O_DIM 64

// bf16 smem pitches chosen for conflict-free ldmatrix:
//   x: 264 bf16 = 528B = 33 16B-chunks (stride 33 mod 32 = 1)
//   W: 72 bf16  = 144B = 9 chunks      (stride 9 coprime 32)
#define XPITCH 264
#define WPITCH 72

#define WH_OFF   0u        // 64*144 = 9216
#define WL_OFF   9216u
#define BIAS_OFF 18432u    // 256B
#define XH_OFF   18944u    // 64*528 = 33792
#define XL_OFF   52736u    //          33792 -> 86528
#define OUT_OFF  18944u    // reuse x region: 64 rows * 1040B = 66560
#define OPITCH   260       // floats; 260 mod 32 = 4 -> conflict-free scatter
#define SMEM_BYTES 86528

static __device__ __forceinline__ uint32_t s2u(const void* p) {
    uint32_t a;
    asm("{ .reg .u64 t; cvta.to.shared.u64 t, %1; cvt.u32.u64 %0, t; }" : "=r"(a) : "l"(p));
    return a;
}

// split (a,b) into packed bf16x2 hi and lo pairs (a -> low half, memory order)
static __device__ __forceinline__ void split2(float a, float b, uint32_t& hp, uint32_t& lp) {
    __nv_bfloat16 ha = __float2bfloat16(a), hb = __float2bfloat16(b);
    float ra = a - __bfloat162float(ha);
    float rb = b - __bfloat162float(hb);
    __nv_bfloat16 la = __float2bfloat16(ra), lb = __float2bfloat16(rb);
    hp = (uint32_t)__bfloat16_as_ushort(ha) | ((uint32_t)__bfloat16_as_ushort(hb) << 16);
    lp = (uint32_t)__bfloat16_as_ushort(la) | ((uint32_t)__bfloat16_as_ushort(lb) << 16);
}

#define LDSM4(r, addr) \
    asm volatile("ldmatrix.sync.aligned.m8n8.x4.shared.b16 {%0,%1,%2,%3}, [%4];" \
        : "=r"((r)[0]), "=r"((r)[1]), "=r"((r)[2]), "=r"((r)[3]) : "r"(addr))

#define LDSM4T(r, addr) \
    asm volatile("ldmatrix.sync.aligned.m8n8.x4.trans.shared.b16 {%0,%1,%2,%3}, [%4];" \
        : "=r"((r)[0]), "=r"((r)[1]), "=r"((r)[2]), "=r"((r)[3]) : "r"(addr))

#define MMA16816(c, a, b0, b1) \
    asm volatile("mma.sync.aligned.m16n8k16.row.col.f32.bf16.bf16.f32 " \
        "{%0,%1,%2,%3}, {%4,%5,%6,%7}, {%8,%9}, {%0,%1,%2,%3};" \
        : "+f"((c)[0]), "+f"((c)[1]), "+f"((c)[2]), "+f"((c)[3]) \
        : "r"((a)[0]), "r"((a)[1]), "r"((a)[2]), "r"((a)[3]), "r"(b0), "r"(b1))

__global__ void __launch_bounds__(256, 2)
pl_hmma_kernel(const float* __restrict__ x, const float* __restrict__ W,
               const float* __restrict__ b, float* __restrict__ out)
{
    extern __shared__ char base[];
    const uint32_t sb = s2u(base);

    const int tid = threadIdx.x, wid = tid >> 5, lane = tid & 31;
    const int e = blockIdx.x;
    const float* xg = x + (size_t)e * (K_DIM * T_DIM);
    const float* wg = W + (size_t)e * (O_DIM * K_DIM);
    const float* bg = b + (size_t)e * O_DIM;
    float*       og = out + (size_t)e * (O_DIM * T_DIM);

    // ---- Stage W -> (wh, wl) bf16, pitch 72 bf16 ----
    {
        const float4* wg4 = (const float4*)wg;
        #pragma unroll
        for (int i = 0; i < 4; i++) {
            const int f  = tid + (i << 8);         // 0..1023
            const int o  = f >> 4;
            const int kc = (f & 15) << 2;
            float4 v = wg4[f];
            uint2 h, l;
            split2(v.x, v.y, h.x, l.x);
            split2(v.z, v.w, h.y, l.y);
            const uint32_t off = (uint32_t)o * 144u + (uint32_t)kc * 2u;
            *(uint2*)(base + WH_OFF + off) = h;
            *(uint2*)(base + WL_OFF + off) = l;
        }
    }
    // ---- Stage x -> (xh, xl) bf16, pitch 264 bf16 ----
    {
        const float4* xg4 = (const float4*)xg;
        #pragma unroll
        for (int i = 0; i < 16; i++) {
            const int f  = tid + (i << 8);         // 0..4095
            const int k  = f >> 6;
            const int tc = (f & 63) << 2;
            float4 v = xg4[f];
            uint2 h, l;
            split2(v.x, v.y, h.x, l.x);
            split2(v.z, v.w, h.y, l.y);
            const uint32_t off = (uint32_t)k * 528u + (uint32_t)tc * 2u;
            *(uint2*)(base + XH_OFF + off) = h;
            *(uint2*)(base + XL_OFF + off) = l;
        }
    }
    if (tid < 64) *(float*)(base + BIAS_OFF + tid * 4) = bg[tid];
    __syncthreads();

    // ---- Per-warp tile: t in [32*wid, 32*wid+32), o in [0, 64) ----
    const int t_base = wid << 5;
    const int lrow = lane >> 2;        // 0..7
    const int lcol2 = (lane & 3) << 1; // 0,2,4,6

    // c[mi][nj][4]; init with bias
    float c[2][8][4];
    {
        const float* bs = (const float*)(base + BIAS_OFF);
        #pragma unroll
        for (int nj = 0; nj < 8; nj++) {
            const float b0 = bs[nj * 8 + lcol2];
            const float b1 = bs[nj * 8 + lcol2 + 1];
            #pragma unroll
            for (int mi = 0; mi < 2; mi++) {
                c[mi][nj][0] = b0; c[mi][nj][1] = b1;
                c[mi][nj][2] = b0; c[mi][nj][3] = b1;
            }
        }
    }

    // ldmatrix thread-row assignment: mat = lane/8, r = lane%8
    const int lm = lane >> 3, lr = lane & 7;

    #pragma unroll
    for (int ks = 0; ks < 4; ks++) {
        // A fragments (ldmatrix.x4.trans on x[k][t]):
        //   mat0:(k r, t+0) mat1:(k r, t+8) mat2:(k 8+r, t+0) mat3:(k 8+r, t+8)
        uint32_t ah[2][4], al[2][4];
        #pragma unroll
        for (int mi = 0; mi < 2; mi++) {
            const int krow = ks * 16 + ((lm & 2) ? 8 : 0) + lr;
            const int tcol = t_base + mi * 16 + ((lm & 1) ? 8 : 0);
            const uint32_t ao = (uint32_t)krow * 528u + (uint32_t)tcol * 2u;
            LDSM4T(ah[mi], sb + XH_OFF + ao);
            LDSM4T(al[mi], sb + XL_OFF + ao);
        }
        #pragma unroll
        for (int njp = 0; njp < 4; njp++) {
            // B fragments (ldmatrix.x4 on W[o][k]):
            //   mat0:(o j*16+r, k+0) mat1:(o j*16+r, k+8) mat2:(o j*16+8+r, k+0) mat3:+8
            const int orow = njp * 16 + ((lm & 2) ? 8 : 0) + lr;
            const int kcol = ks * 16 + ((lm & 1) ? 8 : 0);
            const uint32_t bo = (uint32_t)orow * 144u + (uint32_t)kcol * 2u;
            uint32_t bh[4], bl[4];
            LDSM4(bh, sb + WH_OFF + bo);
            LDSM4(bl, sb + WL_OFF + bo);
            #pragma unroll
            for (int mi = 0; mi < 2; mi++) {
                MMA16816(c[mi][2 * njp],     ah[mi], bh[0], bh[1]);
                MMA16816(c[mi][2 * njp],     al[mi], bh[0], bh[1]);
                MMA16816(c[mi][2 * njp],     ah[mi], bl[0], bl[1]);
                MMA16816(c[mi][2 * njp + 1], ah[mi], bh[2], bh[3]);
                MMA16816(c[mi][2 * njp + 1], al[mi], bh[2], bh[3]);
                MMA16816(c[mi][2 * njp + 1], ah[mi], bl[2], bl[3]);
            }
        }
    }

    // ---- Epilogue: scatter c -> smem [o][t] (pitch 260 fl, conflict-free), then
    //      coalesced float4 stores to out ----
    __syncthreads();   // all warps done reading x smem (region reused)
    float* outp = (float*)(base + OUT_OFF);
    #pragma unroll
    for (int mi = 0; mi < 2; mi++)
        #pragma unroll
        for (int nj = 0; nj < 8; nj++)
            #pragma unroll
            for (int q = 0; q < 4; q++) {
                const int t = t_base + mi * 16 + lrow + ((q & 2) ? 8 : 0);
                const int o = nj * 8 + lcol2 + (q & 1);
                outp[o * OPITCH + t] = c[mi][nj][q];
            }
    __syncthreads();

    float4* og4 = (float4*)og;
    #pragma unroll
    for (int i = 0; i < 16; i++) {
        const int idx  = tid + (i << 8);      // 0..4095 float4s
        const int row  = idx >> 6;            // o
        const int col4 = idx & 63;
        og4[row * 64 + col4] =
            *(const float4*)(base + OUT_OFF + (uint32_t)row * 1040u + (uint32_t)col4 * 16u);
    }
}

extern "C" void kernel_launch(void* const* d_in, const int* in_sizes, int n_in,
                              void* d_out, int out_size) {
    const float* x = (const float*)d_in[0];   // [E, 64, 256]
    const float* W = (const float*)d_in[1];   // [E, 64, 64]
    const float* b = (const float*)d_in[2];   // [E, 64]
    float*       o = (float*)d_out;           // [E, 64, 256]

    const int E = in_sizes[0] / (K_DIM * T_DIM);

    cudaFuncSetAttribute(pl_hmma_kernel,
                         cudaFuncAttributeMaxDynamicSharedMemorySize, SMEM_BYTES);
    pl_hmma_kernel<<<E, 256, SMEM_BYTES>>>(x, W, b, o);
}

// round 10
// speedup vs baseline: 1.2788x; 1.2182x over previous
#include <cuda_runtime.h>
#include <cuda_bf16.h>
#include <cstdint>

// Per edge: out[o][t] = sum_k W[o][k] * x[k][t] + b[o],  O=K=64, T=256, E=10000
// mma.sync m16n8k16 bf16, 3-term split: D = xh*wh + xl*wh + xh*wl (rel ~2^-18).
// R10: one CTA per HALF-edge (128 t) -> smem 52.5KB, 4 CTAs/SM, occ 50%.
//   A = x^T (ldmatrix.trans on native x[k][t]), B = W[o][k] (ldmatrix).

#define T_DIM 256
#define K_DIM 64
#define O_DIM 64

// smem pitches (16B-chunk strides odd/coprime-32 => conflict-free ldmatrix):
//   x: 136 bf16 = 272B = 17 chunks;  W: 72 bf16 = 144B = 9 chunks
#define WH_OFF   0u        // 64*144 = 9216
#define WL_OFF   9216u
#define BIAS_OFF 18432u    // 256B, pad to 18944
#define XH_OFF   18944u    // 64*272 = 17408 -> 36352
#define XL_OFF   36352u    // -> 53760
#define OUT_OFF  18944u    // reuse x region: 64 rows * 528B = 33792 -> 52736 (< 53760)
#define OPITCH_F 132       // floats; 132 mod 32 = 4 -> conflict-free scatter
#define SMEM_BYTES 53760

static __device__ __forceinline__ uint32_t s2u(const void* p) {
    uint32_t a;
    asm("{ .reg .u64 t; cvta.to.shared.u64 t, %1; cvt.u32.u64 %0, t; }" : "=r"(a) : "l"(p));
    return a;
}

// split (a,b) into packed bf16x2 hi and lo pairs (a -> low half, memory order)
static __device__ __forceinline__ void split2(float a, float b, uint32_t& hp, uint32_t& lp) {
    __nv_bfloat16 ha = __float2bfloat16(a), hb = __float2bfloat16(b);
    float ra = a - __bfloat162float(ha);
    float rb = b - __bfloat162float(hb);
    __nv_bfloat16 la = __float2bfloat16(ra), lb = __float2bfloat16(rb);
    hp = (uint32_t)__bfloat16_as_ushort(ha) | ((uint32_t)__bfloat16_as_ushort(hb) << 16);
    lp = (uint32_t)__bfloat16_as_ushort(la) | ((uint32_t)__bfloat16_as_ushort(lb) << 16);
}

#define LDSM4(r, addr) \
    asm volatile("ldmatrix.sync.aligned.m8n8.x4.shared.b16 {%0,%1,%2,%3}, [%4];" \
        : "=r"((r)[0]), "=r"((r)[1]), "=r"((r)[2]), "=r"((r)[3]) : "r"(addr))

#define LDSM4T(r, addr) \
    asm volatile("ldmatrix.sync.aligned.m8n8.x4.trans.shared.b16 {%0,%1,%2,%3}, [%4];" \
        : "=r"((r)[0]), "=r"((r)[1]), "=r"((r)[2]), "=r"((r)[3]) : "r"(addr))

#define MMA16816(c, a, b0, b1) \
    asm volatile("mma.sync.aligned.m16n8k16.row.col.f32.bf16.bf16.f32 " \
        "{%0,%1,%2,%3}, {%4,%5,%6,%7}, {%8,%9}, {%0,%1,%2,%3};" \
        : "+f"((c)[0]), "+f"((c)[1]), "+f"((c)[2]), "+f"((c)[3]) \
        : "r"((a)[0]), "r"((a)[1]), "r"((a)[2]), "r"((a)[3]), "r"(b0), "r"(b1))

__global__ void __launch_bounds__(256, 4)
pl_hmma_half_kernel(const float* __restrict__ x, const float* __restrict__ W,
                    const float* __restrict__ b, float* __restrict__ out)
{
    extern __shared__ char base[];
    const uint32_t sb = s2u(base);

    const int tid = threadIdx.x, wid = tid >> 5, lane = tid & 31;
    const int e  = blockIdx.x >> 1;          // edge
    const int th = blockIdx.x & 1;           // t-half: siblings adjacent -> W L2-hits
    const float* xg = x + (size_t)e * (K_DIM * T_DIM) + th * 128;
    const float* wg = W + (size_t)e * (O_DIM * K_DIM);
    const float* bg = b + (size_t)e * O_DIM;
    float*       og = out + (size_t)e * (O_DIM * T_DIM) + th * 128;

    // ---- Stage W -> (wh, wl) bf16, pitch 144B ----
    {
        const float4* wg4 = (const float4*)wg;
        #pragma unroll
        for (int i = 0; i < 4; i++) {
            const int f  = tid + (i << 8);         // 0..1023
            const int o  = f >> 4;
            const int kc = f & 15;                 // float4 within row
            float4 v = wg4[f];
            uint2 h, l;
            split2(v.x, v.y, h.x, l.x);
            split2(v.z, v.w, h.y, l.y);
            const uint32_t off = (uint32_t)o * 144u + (uint32_t)kc * 8u;
            *(uint2*)(base + WH_OFF + off) = h;
            *(uint2*)(base + WL_OFF + off) = l;
        }
    }
    // ---- Stage x half -> (xh, xl) bf16, pitch 272B (128 t per row) ----
    {
        #pragma unroll
        for (int i = 0; i < 8; i++) {
            const int f  = tid + (i << 8);         // 0..2047 float4s
            const int k  = f >> 5;                 // 32 float4 per local row
            const int c4 = f & 31;
            float4 v = *(const float4*)(xg + (size_t)k * T_DIM + (c4 << 2));
            uint2 h, l;
            split2(v.x, v.y, h.x, l.x);
            split2(v.z, v.w, h.y, l.y);
            const uint32_t off = (uint32_t)k * 272u + (uint32_t)c4 * 8u;
            *(uint2*)(base + XH_OFF + off) = h;
            *(uint2*)(base + XL_OFF + off) = l;
        }
    }
    if (tid < 64) *(float*)(base + BIAS_OFF + tid * 4) = bg[tid];
    __syncthreads();

    // ---- Per-warp tile: t_loc in [16*wid, 16*wid+16), o in [0, 64) ----
    const int t_loc = wid << 4;
    const int lrow = lane >> 2;        // 0..7
    const int lcol2 = (lane & 3) << 1; // 0,2,4,6
    const int lm = lane >> 3, lr = lane & 7;

    float c[8][4];
    {
        const float* bs = (const float*)(base + BIAS_OFF);
        #pragma unroll
        for (int nj = 0; nj < 8; nj++) {
            const float b0 = bs[nj * 8 + lcol2];
            const float b1 = bs[nj * 8 + lcol2 + 1];
            c[nj][0] = b0; c[nj][1] = b1; c[nj][2] = b0; c[nj][3] = b1;
        }
    }

    #pragma unroll
    for (int ks = 0; ks < 4; ks++) {
        // A frags (trans): mats (k r,t)(k r,t+8)(k+8,t)(k+8,t+8)
        const int krow = ks * 16 + ((lm & 2) ? 8 : 0) + lr;
        const int tcol = t_loc + ((lm & 1) ? 8 : 0);
        const uint32_t ao = (uint32_t)krow * 272u + (uint32_t)tcol * 2u;
        uint32_t ah[4], al[4];
        LDSM4T(ah, sb + XH_OFF + ao);
        LDSM4T(al, sb + XL_OFF + ao);

        #pragma unroll
        for (int njp = 0; njp < 4; njp++) {
            const int orow = njp * 16 + ((lm & 2) ? 8 : 0) + lr;
            const int kcol = ks * 16 + ((lm & 1) ? 8 : 0);
            const uint32_t bo = (uint32_t)orow * 144u + (uint32_t)kcol * 2u;
            uint32_t bh[4], bl[4];
            LDSM4(bh, sb + WH_OFF + bo);
            LDSM4(bl, sb + WL_OFF + bo);
            MMA16816(c[2 * njp],     ah, bh[0], bh[1]);
            MMA16816(c[2 * njp],     al, bh[0], bh[1]);
            MMA16816(c[2 * njp],     ah, bl[0], bl[1]);
            MMA16816(c[2 * njp + 1], ah, bh[2], bh[3]);
            MMA16816(c[2 * njp + 1], al, bh[2], bh[3]);
            MMA16816(c[2 * njp + 1], ah, bl[2], bl[3]);
        }
    }

    // ---- Epilogue: scatter c -> smem [o][t_loc] (pitch 132 fl), then coalesced stores ----
    __syncthreads();   // x smem region reused
    float* outp = (float*)(base + OUT_OFF);
    #pragma unroll
    for (int nj = 0; nj < 8; nj++)
        #pragma unroll
        for (int q = 0; q < 4; q++) {
            const int t = t_loc + lrow + ((q & 2) ? 8 : 0);
            const int o = nj * 8 + lcol2 + (q & 1);
            outp[o * OPITCH_F + t] = c[nj][q];
        }
    __syncthreads();

    #pragma unroll
    for (int i = 0; i < 8; i++) {
        const int idx = tid + (i << 8);       // 0..2047 float4s
        const int row = idx >> 5;             // o
        const int c4  = idx & 31;             // local t float4
        *(float4*)(og + (size_t)row * T_DIM + (c4 << 2)) =
            *(const float4*)(base + OUT_OFF + (uint32_t)row * 528u + (uint32_t)c4 * 16u);
    }
}

extern "C" void kernel_launch(void* const* d_in, const int* in_sizes, int n_in,
                              void* d_out, int out_size) {
    const float* x = (const float*)d_in[0];   // [E, 64, 256]
    const float* W = (const float*)d_in[1];   // [E, 64, 64]
    const float* b = (const float*)d_in[2];   // [E, 64]
    float*       o = (float*)d_out;           // [E, 64, 256]

    const int E = in_sizes[0] / (K_DIM * T_DIM);

    cudaFuncSetAttribute(pl_hmma_half_kernel,
                         cudaFuncAttributeMaxDynamicSharedMemorySize, SMEM_BYTES);
    pl_hmma_half_kernel<<<2 * E, 256, SMEM_BYTES>>>(x, W, b, o);
}